// round 15
// baseline (speedup 1.0000x reference)
#include <cuda_runtime.h>
#include <cuda_bf16.h>
#include <math.h>
#include <stdint.h>

#define NTOK   131072
#define DIM    256
#define NCODE  1024
#define ND     (NTOK*DIM)

// smem: A = 128 tok x 256B = 32KB ; B = 2 x (128 codes x 256B) = 64KB
#define SMEM_A_BYTES   32768
#define SMEM_B_STAGE   32768
#define SMEM_TOTAL     (SMEM_A_BYTES + 2*SMEM_B_STAGE)   // 98304

#define NCAND  8
#define BIAS   134217728.0f  // 2^27 > max |score| ~5.1e7 -> acc always positive

// ---------------- persistent device scratch ----------------
__device__ float          g_cn[NCODE*DIM];      // normalized codebook fp32
__device__ uint8_t        g_cb_f8[NCODE*DIM];   // e4m3 codebook (global scale)
__device__ unsigned int   g_cmax;               // max |cn| as float bits
__device__ int            g_cand[NTOK*NCAND];   // top-8 candidate codes per token
__device__ unsigned int   g_counts[NCODE];
__device__ double         g_sumsq;

__device__ __forceinline__ uint32_t smem_u32(const void* p) {
    uint32_t a;
    asm("{ .reg .u64 t; cvta.to.shared.u64 t, %1; cvt.u32.u64 %0, t; }" : "=r"(a) : "l"(p));
    return a;
}

#define LDSM4(r0,r1,r2,r3,a) \
    asm volatile("ldmatrix.sync.aligned.m8n8.x4.shared.b16 {%0,%1,%2,%3}, [%4];" \
        : "=r"(r0),"=r"(r1),"=r"(r2),"=r"(r3) : "r"(a))

#define MMAF8(d,a0,a1,a2,a3,b0,b1) \
    asm volatile("mma.sync.aligned.m16n8k32.row.col.f32.e4m3.e4m3.f32 " \
        "{%0,%1,%2,%3},{%4,%5,%6,%7},{%8,%9},{%0,%1,%2,%3};" \
        : "+f"((d)[0]),"+f"((d)[1]),"+f"((d)[2]),"+f"((d)[3]) \
        : "r"(a0),"r"(a1),"r"(a2),"r"(a3),"r"(b0),"r"(b1))

#define CP_ASYNC16(dst, src) \
    asm volatile("cp.async.cg.shared.global [%0], [%1], 16;" :: "r"(dst), "l"(src))
#define CP_COMMIT() asm volatile("cp.async.commit_group;" ::: "memory")
#define CP_WAIT0()  asm volatile("cp.async.wait_group 0;"  ::: "memory")

// pack 4 scaled floats into 4 e4m3 bytes (a in low byte)
__device__ __forceinline__ uint32_t pack4_e4m3(float a, float b, float c, float d, float s) {
    uint16_t lo, hi;
    float a_s = a*s, b_s = b*s, c_s = c*s, d_s = d*s;
    asm("cvt.rn.satfinite.e4m3x2.f32 %0, %1, %2;" : "=h"(lo) : "f"(b_s), "f"(a_s));
    asm("cvt.rn.satfinite.e4m3x2.f32 %0, %1, %2;" : "=h"(hi) : "f"(d_s), "f"(c_s));
    return (uint32_t)lo | ((uint32_t)hi << 16);
}

// ============================================================
__global__ void k_init() {
    int t = threadIdx.x;
    if (t < NCODE) g_counts[t] = 0u;
    if (t == 0) { g_sumsq = 0.0; g_cmax = 0u; }
}

// ============================================================
__global__ void k_norm(const float* __restrict__ w) {
    int row = blockIdx.x;
    int t   = threadIdx.x;                       // 64 threads
    float4 v = ((const float4*)(w + row*DIM))[t];
    float s  = v.x*v.x + v.y*v.y + v.z*v.z + v.w*v.w;
    #pragma unroll
    for (int o = 16; o > 0; o >>= 1) s += __shfl_xor_sync(0xffffffffu, s, o);
    __shared__ float ss[2];
    if ((t & 31) == 0) ss[t >> 5] = s;
    __syncthreads();
    float n = sqrtf(ss[0] + ss[1]);
    float r = 1.0f / fmaxf(n, 1e-12f);
    float c[4] = { v.x*r, v.y*r, v.z*r, v.w*r };
    ((float4*)(g_cn + row*DIM))[t] = make_float4(c[0], c[1], c[2], c[3]);
    float am = fmaxf(fmaxf(fabsf(c[0]), fabsf(c[1])), fmaxf(fabsf(c[2]), fabsf(c[3])));
    #pragma unroll
    for (int o = 16; o > 0; o >>= 1) am = fmaxf(am, __shfl_xor_sync(0xffffffffu, am, o));
    if ((t & 31) == 0) atomicMax(&g_cmax, __float_as_uint(am));
}

// ============================================================
__global__ void k_quantc() {
    int row = blockIdx.x, t = threadIdx.x;       // 64 threads
    float cmax = __uint_as_float(g_cmax);
    float s    = (cmax > 0.f) ? 448.0f / cmax : 0.f;
    float4 v = ((const float4*)(g_cn + row*DIM))[t];
    ((uint32_t*)(g_cb_f8 + row*DIM))[t] = pack4_e4m3(v.x, v.y, v.z, v.w, s);
}

// ============================================================
// fp8 e4m3 mma.sync GEMM. CTA: 128 tokens, 512 threads,
// 16 warps (8m x 2n), warp tile 16 x 64 (two 32-code halves,
// acc[16] each). 8 N-tile stages of 128 codes, B double-
// buffered via cp.async. Packed uint depth-4 chain fold.
// 2 CTAs/SM -> 50% occupancy. ~58 regs, no spills.
// ============================================================
__global__ void __launch_bounds__(512, 2)
k_gemm(const float* __restrict__ z) {
    extern __shared__ char sm[];
    char* As = sm;
    const uint32_t sb = smem_u32(sm);

    const int tid  = threadIdx.x;
    const int wid  = tid >> 5, lane = tid & 31;
    const int wm   = wid & 7,  wn   = wid >> 3;
    const int mBase = blockIdx.x * 128;

    // ---- A fill: per-token max-abs scale, quantize to e4m3, swizzled ----
    {
        #pragma unroll 1
        for (int i = 0; i < 8; i++) {
            int tok = wid*8 + i;
            const float4* zrow = (const float4*)(z + (size_t)(mBase + tok)*DIM);
            float4 va = zrow[lane];
            float4 vb = zrow[lane + 32];
            float m = fmaxf(fmaxf(fabsf(va.x), fabsf(va.y)), fmaxf(fabsf(va.z), fabsf(va.w)));
            m = fmaxf(m, fmaxf(fmaxf(fabsf(vb.x), fabsf(vb.y)), fmaxf(fabsf(vb.z), fabsf(vb.w))));
            #pragma unroll
            for (int o = 16; o > 0; o >>= 1) m = fmaxf(m, __shfl_xor_sync(0xffffffffu, m, o));
            float s = (m > 0.f) ? 448.0f / m : 0.f;
            uint32_t u0 = pack4_e4m3(va.x, va.y, va.z, va.w, s);
            uint32_t u1 = pack4_e4m3(vb.x, vb.y, vb.z, vb.w, s);
            int base = tok*256, xo = (tok & 7)*16;
            *(uint32_t*)(As + base + ((lane*4)       ^ xo)) = u0;
            *(uint32_t*)(As + base + ((128 + lane*4) ^ xo)) = u1;
        }
    }

    // ---- B cp.async: stage = 128 rows x 256B; 4x16B chunks/thread ----
    const int r0 = tid >> 4, gr = tid & 15;      // r0 0..31, gr chunk 0..15
    const uint32_t bdst0 = sb + SMEM_A_BYTES +
        (uint32_t)(r0*256 + ((gr*16) ^ ((r0 & 7)*16)));
    const char* bsrc0 = (const char*)g_cb_f8 + (size_t)r0*256 + gr*16;

    // prologue: stage 0 (4 blocks of 32 rows)
    #pragma unroll
    for (int j = 0; j < 4; j++)
        CP_ASYNC16(bdst0 + j*8192u, bsrc0 + (size_t)j*8192);
    CP_COMMIT();

    // ---- per-lane ldmatrix address components ----
    const int lr  = lane & 7;
    const int l8  = (lane >> 3) & 1;
    const int l16 = (lane >> 4) & 1;
    const uint32_t aBase = sb + (uint32_t)(wm*16 + lr + l8*8) * 256;
    const uint32_t kaddA = (uint32_t)(l16 * 16);
    const uint32_t bBase = sb + SMEM_A_BYTES + (uint32_t)(wn*64 + l16*8 + lr) * 256;
    const uint32_t kaddB = (uint32_t)(l8 * 16);
    const uint32_t lXor  = (uint32_t)(lr * 16);

    // depth-4 packed uint chains per row-slot (rg=0,1)
    // entry = (score_bits & ~0x7F) | (nt<<4) | (t8_full<<1) | e
    uint32_t c1[2], c2[2], c3[2], c4[2];
    #pragma unroll
    for (int s = 0; s < 2; s++) { c1[s]=c2[s]=c3[s]=c4[s]=0u; }

    #pragma unroll 1
    for (int nt = 0; nt < 8; nt++) {
        CP_WAIT0();
        __syncthreads();

        if (nt + 1 < 8) {
            uint32_t boff = (uint32_t)((nt + 1) & 1)*SMEM_B_STAGE;
            const char* src = bsrc0 + (size_t)(nt + 1)*32768;
            #pragma unroll
            for (int j = 0; j < 4; j++)
                CP_ASYNC16(bdst0 + boff + j*8192u, src + (size_t)j*8192);
            CP_COMMIT();
        }

        const uint32_t bufB   = (uint32_t)(nt & 1)*SMEM_B_STAGE;
        const uint32_t ntbits = (uint32_t)(nt << 4);

        // ---- two 32-code halves of the 16x64 warp tile ----
        #pragma unroll
        for (int h = 0; h < 2; h++) {
            float acc[16];
            #pragma unroll
            for (int i = 0; i < 16; i++) acc[i] = BIAS;

            const uint32_t bHalf = bBase + bufB + (uint32_t)(h*8192);

            #pragma unroll
            for (int kk = 0; kk < 8; kk++) {
                uint32_t kb = (uint32_t)(kk*32);
                uint32_t aAddr = aBase + ((kb + kaddA) ^ lXor);
                uint32_t a0[4];
                LDSM4(a0[0], a0[1], a0[2], a0[3], aAddr);

                uint32_t bAddr = bHalf + ((kb + kaddB) ^ lXor);
                uint32_t bf[8];
                LDSM4(bf[0], bf[1], bf[2], bf[3], bAddr);
                LDSM4(bf[4], bf[5], bf[6], bf[7], bAddr + 4096u);
                #pragma unroll
                for (int tt = 0; tt < 4; tt++) {
                    uint32_t b0 = bf[(tt >> 1)*4 + (tt & 1)*2 + 0];
                    uint32_t b1 = bf[(tt >> 1)*4 + (tt & 1)*2 + 1];
                    MMAF8(&acc[tt*4], a0[0], a0[1], a0[2], a0[3], b0, b1);
                }
            }

            // ---- fold 16 values into the 2 row-slot chains ----
            #pragma unroll
            for (int rg = 0; rg < 2; rg++) {
                #pragma unroll
                for (int tt = 0; tt < 4; tt++) {
                    #pragma unroll
                    for (int e = 0; e < 2; e++) {
                        int t8f = h*4 + tt;      // 0..7
                        uint32_t u = (__float_as_uint(acc[tt*4 + rg*2 + e]) & 0xFFFFFF80u)
                                     | (ntbits | (uint32_t)(t8f*2 + e));
                        uint32_t d1 = min(c1[rg], u);  c1[rg] = max(c1[rg], u);
                        uint32_t d2 = min(c2[rg], d1); c2[rg] = max(c2[rg], d1);
                        uint32_t d3 = min(c3[rg], d2); c3[rg] = max(c3[rg], d2);
                        c4[rg] = max(c4[rg], d3);
                    }
                }
            }
        }
    }

    // ---- dump per-thread top-4 to smem, merge to token top-8 ----
    __syncthreads();
    uint32_t* red = (uint32_t*)sm;               // [128 tok][8 q][4]
    {
        int q = wn*4 + (lane & 3);
        int row = lane >> 2;
        #pragma unroll
        for (int rg = 0; rg < 2; rg++) {
            int tl = wm*16 + rg*8 + row;
            uint32_t* e = red + (tl*8 + q)*4;
            e[0]=c1[rg]; e[1]=c2[rg]; e[2]=c3[rg]; e[3]=c4[rg];
        }
    }
    __syncthreads();
    if (tid < 128) {
        uint32_t top[NCAND];
        int      topq[NCAND];
        #pragma unroll
        for (int j = 0; j < NCAND; j++) { top[j] = 0u; topq[j] = 0; }
        const uint32_t* e = red + tid*32;
        #pragma unroll 4
        for (int j = 0; j < 32; j++) {
            uint32_t u = e[j];
            if (u > top[NCAND-1]) {
                top[NCAND-1] = u; topq[NCAND-1] = j >> 2;
                #pragma unroll
                for (int t = NCAND-1; t > 0; t--) {
                    if (top[t] > top[t-1]) {
                        uint32_t tu = top[t-1]; top[t-1] = top[t]; top[t] = tu;
                        int tq = topq[t-1]; topq[t-1] = topq[t]; topq[t] = tq;
                    }
                }
            }
        }
        int token = mBase + tid;
        #pragma unroll
        for (int j = 0; j < NCAND; j++) {
            uint32_t u = top[j];
            int q   = topq[j];
            int nt_ = (int)((u >> 4) & 7u);
            int t8_ = (int)((u >> 1) & 7u);
            int e_  = (int)(u & 1u);
            g_cand[token*NCAND + j] =
                nt_*128 + (q >> 2)*64 + t8_*8 + (q & 3)*2 + e_;
        }
    }
}

// ============================================================
// fp32 rescore of 8 candidates + gather z_q + loss + counts
// one warp per token
// ============================================================
__global__ void k_fin(const float* __restrict__ z, const float* __restrict__ w,
                      float* __restrict__ out) {
    int wp = threadIdx.x >> 5, lane = threadIdx.x & 31;
    int token = blockIdx.x*8 + wp;

    int cand[NCAND];
    #pragma unroll
    for (int q = 0; q < NCAND; q++) cand[q] = g_cand[token*NCAND + q];

    const float4* zz = (const float4*)(z + (size_t)token*DIM);
    float4 zv[2];
    float d[NCAND];
    #pragma unroll
    for (int q = 0; q < NCAND; q++) d[q] = 0.f;
    #pragma unroll
    for (int rr = 0; rr < 2; rr++) {
        int j = lane + rr*32;
        zv[rr] = zz[j];
        #pragma unroll
        for (int q = 0; q < NCAND; q++) {
            float4 a = ((const float4*)(g_cn + (size_t)cand[q]*DIM))[j];
            d[q] += zv[rr].x*a.x + zv[rr].y*a.y + zv[rr].z*a.z + zv[rr].w*a.w;
        }
    }
    #pragma unroll
    for (int o = 16; o > 0; o >>= 1)
        #pragma unroll
        for (int q = 0; q < NCAND; q++)
            d[q] += __shfl_xor_sync(0xffffffffu, d[q], o);

    float bd = -3.4e38f; int win = 0x7fffffff;
    #pragma unroll
    for (int q = 0; q < NCAND; q++)
        if (d[q] > bd || (d[q] == bd && cand[q] < win)) { bd = d[q]; win = cand[q]; }

    const float4* e  = (const float4*)(w + (size_t)win*DIM);
    float4*       o4 = (float4*)(out + (size_t)token*DIM);
    float s = 0.f;
    #pragma unroll
    for (int rr = 0; rr < 2; rr++) {
        int j = lane + rr*32;
        float4 ev = e[j];
        o4[j] = ev;
        float dx = ev.x - zv[rr].x, dy = ev.y - zv[rr].y;
        float dz = ev.z - zv[rr].z, dw = ev.w - zv[rr].w;
        s += dx*dx + dy*dy + dz*dz + dw*dw;
    }
    #pragma unroll
    for (int o = 16; o > 0; o >>= 1) s += __shfl_xor_sync(0xffffffffu, s, o);
    if (lane == 0) {
        out[ND + 2 + token] = (float)win;
        atomicAdd(&g_counts[win], 1u);
    }
    __shared__ float ps[8];
    if (lane == 0) ps[wp] = s;
    __syncthreads();
    if (threadIdx.x == 0) {
        float tot = 0.f;
        #pragma unroll
        for (int i = 0; i < 8; i++) tot += ps[i];
        atomicAdd(&g_sumsq, (double)tot);
    }
}

// ============================================================
__global__ void k_final(float* __restrict__ out) {
    int t = threadIdx.x;                         // 1024 threads
    float p    = (float)g_counts[t] / (float)NTOK;
    float term = p * logf(p + 1e-10f);
    #pragma unroll
    for (int o = 16; o > 0; o >>= 1) term += __shfl_xor_sync(0xffffffffu, term, o);
    __shared__ float ws[32];
    if ((t & 31) == 0) ws[t >> 5] = term;
    __syncthreads();
    if (t < 32) {
        float v = ws[t];
        #pragma unroll
        for (int o = 16; o > 0; o >>= 1) v += __shfl_xor_sync(0xffffffffu, v, o);
        if (t == 0) {
            out[ND]     = (float)(1.25 * (g_sumsq / (double)ND));
            out[ND + 1] = expf(-v);
        }
    }
}

// ============================================================
extern "C" void kernel_launch(void* const* d_in, const int* in_sizes, int n_in,
                              void* d_out, int out_size) {
    const float* z = (const float*)d_in[0];      // [131072, 256]
    const float* w = (const float*)d_in[1];      // [1024, 256]
    float* out = (float*)d_out;

    cudaFuncSetAttribute(k_gemm, cudaFuncAttributeMaxDynamicSharedMemorySize, SMEM_TOTAL);

    k_init  <<<1, 1024>>>();
    k_norm  <<<NCODE, 64>>>(w);
    k_quantc<<<NCODE, 64>>>();
    k_gemm  <<<NTOK/128, 512, SMEM_TOTAL>>>(z);
    k_fin   <<<NTOK/8, 256>>>(z, w, out);
    k_final <<<1, 1024>>>(out);
}

// round 16
// speedup vs baseline: 1.7299x; 1.7299x over previous
#include <cuda_runtime.h>
#include <cuda_bf16.h>
#include <math.h>
#include <stdint.h>

#define NTOK   131072
#define DIM    256
#define NCODE  1024
#define ND     (NTOK*DIM)

// smem: A = 128 tok x 256B = 32KB ; B = 2 x (64 codes x 256B) = 32KB
#define SMEM_A_BYTES   32768
#define SMEM_B_STAGE   16384
#define SMEM_TOTAL     (SMEM_A_BYTES + 2*SMEM_B_STAGE)   // 65536
#define NTILES 16            // 16 N-tiles of 64 codes

#define NCAND  8
#define BIAS   134217728.0f  // 2^27 > max |score| ~5.1e7 -> acc always positive

// ---------------- persistent device scratch ----------------
__device__ float          g_cn[NCODE*DIM];      // normalized codebook fp32
__device__ uint8_t        g_cb_f8[NCODE*DIM];   // e4m3 codebook (global scale)
__device__ unsigned int   g_cmax;               // max |cn| as float bits
__device__ int            g_cand[NTOK*NCAND];   // top-8 candidate codes per token
__device__ unsigned int   g_counts[NCODE];
__device__ double         g_sumsq;

__device__ __forceinline__ uint32_t smem_u32(const void* p) {
    uint32_t a;
    asm("{ .reg .u64 t; cvta.to.shared.u64 t, %1; cvt.u32.u64 %0, t; }" : "=r"(a) : "l"(p));
    return a;
}

#define LDSM4(r0,r1,r2,r3,a) \
    asm volatile("ldmatrix.sync.aligned.m8n8.x4.shared.b16 {%0,%1,%2,%3}, [%4];" \
        : "=r"(r0),"=r"(r1),"=r"(r2),"=r"(r3) : "r"(a))

#define MMAF8(d,a0,a1,a2,a3,b0,b1) \
    asm volatile("mma.sync.aligned.m16n8k32.row.col.f32.e4m3.e4m3.f32 " \
        "{%0,%1,%2,%3},{%4,%5,%6,%7},{%8,%9},{%0,%1,%2,%3};" \
        : "+f"((d)[0]),"+f"((d)[1]),"+f"((d)[2]),"+f"((d)[3]) \
        : "r"(a0),"r"(a1),"r"(a2),"r"(a3),"r"(b0),"r"(b1))

#define CP_ASYNC16(dst, src) \
    asm volatile("cp.async.cg.shared.global [%0], [%1], 16;" :: "r"(dst), "l"(src))
#define CP_COMMIT() asm volatile("cp.async.commit_group;" ::: "memory")
#define CP_WAIT0()  asm volatile("cp.async.wait_group 0;"  ::: "memory")

// pack 4 scaled floats into 4 e4m3 bytes (a in low byte)
__device__ __forceinline__ uint32_t pack4_e4m3(float a, float b, float c, float d, float s) {
    uint16_t lo, hi;
    float a_s = a*s, b_s = b*s, c_s = c*s, d_s = d*s;
    asm("cvt.rn.satfinite.e4m3x2.f32 %0, %1, %2;" : "=h"(lo) : "f"(b_s), "f"(a_s));
    asm("cvt.rn.satfinite.e4m3x2.f32 %0, %1, %2;" : "=h"(hi) : "f"(d_s), "f"(c_s));
    return (uint32_t)lo | ((uint32_t)hi << 16);
}

// ============================================================
__global__ void k_init() {
    int t = threadIdx.x;
    if (t < NCODE) g_counts[t] = 0u;
    if (t == 0) { g_sumsq = 0.0; g_cmax = 0u; }
}

// ============================================================
__global__ void k_norm(const float* __restrict__ w) {
    int row = blockIdx.x;
    int t   = threadIdx.x;                       // 64 threads
    float4 v = ((const float4*)(w + row*DIM))[t];
    float s  = v.x*v.x + v.y*v.y + v.z*v.z + v.w*v.w;
    #pragma unroll
    for (int o = 16; o > 0; o >>= 1) s += __shfl_xor_sync(0xffffffffu, s, o);
    __shared__ float ss[2];
    if ((t & 31) == 0) ss[t >> 5] = s;
    __syncthreads();
    float n = sqrtf(ss[0] + ss[1]);
    float r = 1.0f / fmaxf(n, 1e-12f);
    float c[4] = { v.x*r, v.y*r, v.z*r, v.w*r };
    ((float4*)(g_cn + row*DIM))[t] = make_float4(c[0], c[1], c[2], c[3]);
    float am = fmaxf(fmaxf(fabsf(c[0]), fabsf(c[1])), fmaxf(fabsf(c[2]), fabsf(c[3])));
    #pragma unroll
    for (int o = 16; o > 0; o >>= 1) am = fmaxf(am, __shfl_xor_sync(0xffffffffu, am, o));
    if ((t & 31) == 0) atomicMax(&g_cmax, __float_as_uint(am));
}

// ============================================================
__global__ void k_quantc() {
    int row = blockIdx.x, t = threadIdx.x;       // 64 threads
    float cmax = __uint_as_float(g_cmax);
    float s    = (cmax > 0.f) ? 448.0f / cmax : 0.f;
    float4 v = ((const float4*)(g_cn + row*DIM))[t];
    ((uint32_t*)(g_cb_f8 + row*DIM))[t] = pack4_e4m3(v.x, v.y, v.z, v.w, s);
}

// ============================================================
// fp8 e4m3 mma.sync GEMM. CTA: 128 tokens, 256 thr, 8 warps
// (4m x 2n), warp tile 32 x 32, 16 N-tile stages of 64 codes,
// B double-buffered via cp.async. 3 CTAs/SM (85-reg cap,
// ~81 demand -> no spills). Exact depth-4 chains, pipes
// balanced FMNMX/IMNMX. Chain stats identical to R12.
// ============================================================
__global__ void __launch_bounds__(256, 3)
k_gemm(const float* __restrict__ z) {
    extern __shared__ char sm[];
    char* As = sm;
    const uint32_t sb = smem_u32(sm);

    const int tid  = threadIdx.x;
    const int wid  = tid >> 5, lane = tid & 31;
    const int wm   = wid & 3,  wn   = wid >> 2;
    const int mBase = blockIdx.x * 128;

    // ---- A fill: per-token max-abs scale, quantize to e4m3, swizzled ----
    {
        #pragma unroll 1
        for (int i = 0; i < 16; i++) {
            int tok = wid*16 + i;
            const float4* zrow = (const float4*)(z + (size_t)(mBase + tok)*DIM);
            float4 va = zrow[lane];
            float4 vb = zrow[lane + 32];
            float m = fmaxf(fmaxf(fabsf(va.x), fabsf(va.y)), fmaxf(fabsf(va.z), fabsf(va.w)));
            m = fmaxf(m, fmaxf(fmaxf(fabsf(vb.x), fabsf(vb.y)), fmaxf(fabsf(vb.z), fabsf(vb.w))));
            #pragma unroll
            for (int o = 16; o > 0; o >>= 1) m = fmaxf(m, __shfl_xor_sync(0xffffffffu, m, o));
            float s = (m > 0.f) ? 448.0f / m : 0.f;
            uint32_t u0 = pack4_e4m3(va.x, va.y, va.z, va.w, s);
            uint32_t u1 = pack4_e4m3(vb.x, vb.y, vb.z, vb.w, s);
            int base = tok*256, xo = (tok & 7)*16;
            *(uint32_t*)(As + base + ((lane*4)       ^ xo)) = u0;
            *(uint32_t*)(As + base + ((128 + lane*4) ^ xo)) = u1;
        }
    }

    // ---- B cp.async: stage = 64 rows x 256B; 4x16B chunks/thread ----
    // dst chunk c = c0 + 4j -> row byte ((c0*16 | j*64) ^ xo); src same byte.
    const int r0 = tid >> 2;                     // row 0..63
    const uint32_t cb16 = (uint32_t)((tid & 3) * 16);
    const uint32_t bxo  = (uint32_t)((r0 & 7) * 16);
    const uint32_t drow = sb + SMEM_A_BYTES + (uint32_t)(r0*256);
    const char* bsrc0 = (const char*)g_cb_f8 + (size_t)r0*256 + cb16;

    // prologue: stage 0
    #pragma unroll
    for (int j = 0; j < 4; j++)
        CP_ASYNC16(drow + ((cb16 | (uint32_t)(j*64)) ^ bxo), bsrc0 + (size_t)j*64);
    CP_COMMIT();

    // ---- per-lane ldmatrix address components ----
    const int lr  = lane & 7;
    const int l8  = (lane >> 3) & 1;
    const int l16 = (lane >> 4) & 1;
    const uint32_t aBase = sb + (uint32_t)(wm*32 + lr + l8*8) * 256;
    const uint32_t kaddA = (uint32_t)(l16 * 16);
    const uint32_t bBase = sb + SMEM_A_BYTES + (uint32_t)(wn*32 + l16*8 + lr) * 256;
    const uint32_t kaddB = (uint32_t)(l8 * 16);
    const uint32_t lXor  = (uint32_t)(lr * 16);

    // depth-4 chains per row-slot s = mt*2+rg, alternating float/uint pipes
    // entry = (score_bits & ~0x7F) | (nt<<3) | (t8<<1) | e
    float    c1f[4], c3f[4];
    uint32_t c2u[4], c4u[4];
    #pragma unroll
    for (int s = 0; s < 4; s++) { c1f[s] = c3f[s] = 0.f; c2u[s] = c4u[s] = 0u; }

    #pragma unroll 1
    for (int nt = 0; nt < NTILES; nt++) {
        CP_WAIT0();
        __syncthreads();

        if (nt + 1 < NTILES) {
            uint32_t boff = (uint32_t)((nt + 1) & 1)*SMEM_B_STAGE;
            const char* src = bsrc0 + (size_t)(nt + 1)*16384;
            #pragma unroll
            for (int j = 0; j < 4; j++)
                CP_ASYNC16(drow + boff + ((cb16 | (uint32_t)(j*64)) ^ bxo),
                           src + (size_t)j*64);
            CP_COMMIT();
        }

        const uint32_t bufB = (uint32_t)(nt & 1)*SMEM_B_STAGE;

        float acc[32];
        #pragma unroll
        for (int i = 0; i < 32; i++) acc[i] = BIAS;

        // ---- compute: 8 k32-steps; warp tile 32 tok x 32 codes ----
        #pragma unroll
        for (int kk = 0; kk < 8; kk++) {
            uint32_t kb = (uint32_t)(kk*32);
            uint32_t aAddr = aBase + ((kb + kaddA) ^ lXor);
            uint32_t a0[4], a1[4];
            LDSM4(a0[0], a0[1], a0[2], a0[3], aAddr);
            LDSM4(a1[0], a1[1], a1[2], a1[3], aAddr + 4096u);

            uint32_t bAddr = bBase + bufB + ((kb + kaddB) ^ lXor);
            #pragma unroll
            for (int gb = 0; gb < 2; gb++) {
                uint32_t bf[4];
                LDSM4(bf[0], bf[1], bf[2], bf[3], bAddr + (uint32_t)gb*4096);
                #pragma unroll
                for (int tt = 0; tt < 2; tt++) {
                    int t8 = gb*2 + tt;
                    MMAF8(&acc[t8*4],      a0[0], a0[1], a0[2], a0[3],
                          bf[tt*2], bf[tt*2 + 1]);
                    MMAF8(&acc[16 + t8*4], a1[0], a1[1], a1[2], a1[3],
                          bf[tt*2], bf[tt*2 + 1]);
                }
            }
        }

        // ---- fold 32 values into the 4 row-slot chains ----
        const uint32_t ntb = (uint32_t)(nt << 3);
        #pragma unroll
        for (int mt = 0; mt < 2; mt++) {
            #pragma unroll
            for (int rg = 0; rg < 2; rg++) {
                const int s = mt*2 + rg;
                #pragma unroll
                for (int t8 = 0; t8 < 4; t8++) {
                    #pragma unroll
                    for (int e = 0; e < 2; e++) {
                        uint32_t u = (__float_as_uint(acc[mt*16 + t8*4 + rg*2 + e])
                                      & 0xFFFFFF80u)
                                     | (ntb | (uint32_t)(t8*2 + e));
                        float xf = __uint_as_float(u);
                        float m1 = fminf(c1f[s], xf);    c1f[s] = fmaxf(c1f[s], xf);
                        uint32_t m1u = __float_as_uint(m1);
                        uint32_t m2 = min(c2u[s], m1u);  c2u[s] = max(c2u[s], m1u);
                        float m2f = __uint_as_float(m2);
                        float m3 = fminf(c3f[s], m2f);   c3f[s] = fmaxf(c3f[s], m2f);
                        c4u[s] = max(c4u[s], __float_as_uint(m3));
                    }
                }
            }
        }
    }

    // ---- dump per-thread top-4 to smem, merge to token top-8 ----
    __syncthreads();
    uint32_t* red = (uint32_t*)sm;               // [128 tok][8 q][4]
    {
        int q = wn*4 + (lane & 3);
        int row = lane >> 2;
        #pragma unroll
        for (int mt = 0; mt < 2; mt++)
            #pragma unroll
            for (int rg = 0; rg < 2; rg++) {
                int s  = mt*2 + rg;
                int tl = wm*32 + mt*16 + rg*8 + row;
                uint32_t* e = red + (tl*8 + q)*4;
                e[0] = __float_as_uint(c1f[s]);
                e[1] = c2u[s];
                e[2] = __float_as_uint(c3f[s]);
                e[3] = c4u[s];
            }
    }
    __syncthreads();
    if (tid < 128) {
        uint32_t top[NCAND];
        int      topq[NCAND];
        #pragma unroll
        for (int j = 0; j < NCAND; j++) { top[j] = 0u; topq[j] = 0; }
        const uint32_t* e = red + tid*32;
        #pragma unroll 4
        for (int j = 0; j < 32; j++) {
            uint32_t u = e[j];
            if (u > top[NCAND-1]) {
                top[NCAND-1] = u; topq[NCAND-1] = j >> 2;
                #pragma unroll
                for (int t = NCAND-1; t > 0; t--) {
                    if (top[t] > top[t-1]) {
                        uint32_t tu = top[t-1]; top[t-1] = top[t]; top[t] = tu;
                        int tq = topq[t-1]; topq[t-1] = topq[t]; topq[t] = tq;
                    }
                }
            }
        }
        int token = mBase + tid;
        #pragma unroll
        for (int j = 0; j < NCAND; j++) {
            uint32_t u = top[j];
            int q   = topq[j];
            int nt_ = (int)((u >> 3) & 15u);
            int t8_ = (int)((u >> 1) & 3u);
            int e_  = (int)(u & 1u);
            g_cand[token*NCAND + j] =
                nt_*64 + (q >> 2)*32 + t8_*8 + (q & 3)*2 + e_;
        }
    }
}

// ============================================================
// fp32 rescore of 8 candidates + gather z_q + loss + counts
// one warp per token
// ============================================================
__global__ void k_fin(const float* __restrict__ z, const float* __restrict__ w,
                      float* __restrict__ out) {
    int wp = threadIdx.x >> 5, lane = threadIdx.x & 31;
    int token = blockIdx.x*8 + wp;

    int cand[NCAND];
    #pragma unroll
    for (int q = 0; q < NCAND; q++) cand[q] = g_cand[token*NCAND + q];

    const float4* zz = (const float4*)(z + (size_t)token*DIM);
    float4 zv[2];
    float d[NCAND];
    #pragma unroll
    for (int q = 0; q < NCAND; q++) d[q] = 0.f;
    #pragma unroll
    for (int rr = 0; rr < 2; rr++) {
        int j = lane + rr*32;
        zv[rr] = zz[j];
        #pragma unroll
        for (int q = 0; q < NCAND; q++) {
            float4 a = ((const float4*)(g_cn + (size_t)cand[q]*DIM))[j];
            d[q] += zv[rr].x*a.x + zv[rr].y*a.y + zv[rr].z*a.z + zv[rr].w*a.w;
        }
    }
    #pragma unroll
    for (int o = 16; o > 0; o >>= 1)
        #pragma unroll
        for (int q = 0; q < NCAND; q++)
            d[q] += __shfl_xor_sync(0xffffffffu, d[q], o);

    float bd = -3.4e38f; int win = 0x7fffffff;
    #pragma unroll
    for (int q = 0; q < NCAND; q++)
        if (d[q] > bd || (d[q] == bd && cand[q] < win)) { bd = d[q]; win = cand[q]; }

    const float4* e  = (const float4*)(w + (size_t)win*DIM);
    float4*       o4 = (float4*)(out + (size_t)token*DIM);
    float s = 0.f;
    #pragma unroll
    for (int rr = 0; rr < 2; rr++) {
        int j = lane + rr*32;
        float4 ev = e[j];
        o4[j] = ev;
        float dx = ev.x - zv[rr].x, dy = ev.y - zv[rr].y;
        float dz = ev.z - zv[rr].z, dw = ev.w - zv[rr].w;
        s += dx*dx + dy*dy + dz*dz + dw*dw;
    }
    #pragma unroll
    for (int o = 16; o > 0; o >>= 1) s += __shfl_xor_sync(0xffffffffu, s, o);
    if (lane == 0) {
        out[ND + 2 + token] = (float)win;
        atomicAdd(&g_counts[win], 1u);
    }
    __shared__ float ps[8];
    if (lane == 0) ps[wp] = s;
    __syncthreads();
    if (threadIdx.x == 0) {
        float tot = 0.f;
        #pragma unroll
        for (int i = 0; i < 8; i++) tot += ps[i];
        atomicAdd(&g_sumsq, (double)tot);
    }
}

// ============================================================
__global__ void k_final(float* __restrict__ out) {
    int t = threadIdx.x;                         // 1024 threads
    float p    = (float)g_counts[t] / (float)NTOK;
    float term = p * logf(p + 1e-10f);
    #pragma unroll
    for (int o = 16; o > 0; o >>= 1) term += __shfl_xor_sync(0xffffffffu, term, o);
    __shared__ float ws[32];
    if ((t & 31) == 0) ws[t >> 5] = term;
    __syncthreads();
    if (t < 32) {
        float v = ws[t];
        #pragma unroll
        for (int o = 16; o > 0; o >>= 1) v += __shfl_xor_sync(0xffffffffu, v, o);
        if (t == 0) {
            out[ND]     = (float)(1.25 * (g_sumsq / (double)ND));
            out[ND + 1] = expf(-v);
        }
    }
}

// ============================================================
extern "C" void kernel_launch(void* const* d_in, const int* in_sizes, int n_in,
                              void* d_out, int out_size) {
    const float* z = (const float*)d_in[0];      // [131072, 256]
    const float* w = (const float*)d_in[1];      // [1024, 256]
    float* out = (float*)d_out;

    cudaFuncSetAttribute(k_gemm, cudaFuncAttributeMaxDynamicSharedMemorySize, SMEM_TOTAL);

    k_init  <<<1, 1024>>>();
    k_norm  <<<NCODE, 64>>>(w);
    k_quantc<<<NCODE, 64>>>();
    k_gemm  <<<NTOK/128, 256, SMEM_TOTAL>>>(z);
    k_fin   <<<NTOK/8, 256>>>(z, w, out);
    k_final <<<1, 1024>>>(out);
}